// round 9
// baseline (speedup 1.0000x reference)
#include <cuda_runtime.h>
#include <cuda_bf16.h>
#include <cuda_fp16.h>
#include <stdint.h>

// LinBnA_int on GB300 via compute_103 (no tcgen05). Hybrid engine:
//   K [0, 2752)   -> legacy HMMA m16n8k16 (fp16 converted in-SMEM, f32 accum — exact)
//   K [2752,4096) -> dp4a on raw int8, issued in the HMMA shadow (int accum)
// out[b,o] = clip((S + t[o]) >> (-n[o]), amin[o], amax[o]) stored as f32.

static constexpr int B_DIM   = 8192;
static constexpr int IN_DIM  = 4096;
static constexpr int OUT_DIM = 4096;

static constexpr int BM = 128;
static constexpr int BN = 128;
static constexpr int RS = 80;                 // fp16 smem row stride (64B data + 16 pad)

static constexpr int H_STAGES = 86;           // 86 * 32 = 2752 K-elems via HMMA
static constexpr int D_CHUNKS = 84;           // 84 * 16 = 1344 K-elems via dp4a
static constexpr int KD_BASE  = H_STAGES * 32;   // 2752
static constexpr int ITERS    = H_STAGES;        // 86

// dynamic SMEM layout
static constexpr int OFF_RAWH = 0;                      // 4 bufs x (A 4KB + B 4KB) = 32768
static constexpr int OFF_RAWD = 32768;                  // 4 bufs x (A 2KB + B 2KB) = 16384
static constexpr int OFF_F16  = 49152;                  // 2 bufs x (A 10240 + B 10240) = 40960
static constexpr int OFF_PAR  = 90112;                  // 4 x 128 x 4 = 2048
static constexpr int SMEM_TOTAL = 92160;

// mode: 0 = raw int8, 1 = int32, 2 = float32, 3 = bfloat16
__device__ int g_mode;
__device__ __align__(128) int8_t g_x[(size_t)B_DIM * IN_DIM];
__device__ __align__(128) int8_t g_w[(size_t)OUT_DIM * IN_DIM];

__global__ void probe_kernel(const void* x)
{
    if (threadIdx.x != 0) return;
    const uint32_t* w32 = (const uint32_t*)x;
    bool is_i32 = true, is_f32 = true;
    for (int i = 0; i < 32; i++) {
        uint32_t u = w32[i];
        int32_t v = (int32_t)u;
        if (!(v >= -128 && v < 128)) is_i32 = false;
        float f = __uint_as_float(u);
        if (!(isfinite(f) && f == truncf(f) && fabsf(f) <= 128.0f)) is_f32 = false;
    }
    bool is_b16 = true;
    const __nv_bfloat16* h = (const __nv_bfloat16*)x;
    for (int i = 0; i < 64; i++) {
        float f = __bfloat162float(h[i]);
        if (!(isfinite(f) && f == truncf(f) && fabsf(f) <= 128.0f)) is_b16 = false;
    }
    int m = 0;
    if (is_f32)      m = 2;
    else if (is_i32) m = 1;
    else if (is_b16) m = 3;
    g_mode = m;
}

__global__ void repack_kernel(const void* xsrc, const void* wsrc)
{
    const int m = g_mode;
    const size_t NX = (size_t)B_DIM * IN_DIM;
    const size_t NW = (size_t)OUT_DIM * IN_DIM;
    const size_t total = NX + NW;
    const size_t stride = (size_t)gridDim.x * blockDim.x;
    for (size_t i = (size_t)blockIdx.x * blockDim.x + threadIdx.x; i < total; i += stride) {
        size_t xi; const void* src; int8_t* dst;
        if (i < NX) { xi = i;      src = xsrc; dst = g_x; }
        else        { xi = i - NX; src = wsrc; dst = g_w; }
        int v;
        if (m == 0)      v = (int)((const int8_t*)src)[xi];
        else if (m == 1) v = ((const int*)src)[xi];
        else if (m == 2) v = (int)((const float*)src)[xi];
        else             v = (int)__bfloat162float(((const __nv_bfloat16*)src)[xi]);
        dst[xi] = (int8_t)v;
    }
}

// ---- helpers --------------------------------------------------------------

__device__ __forceinline__ uint32_t smem_u32(const void* p) {
    uint32_t a;
    asm("{ .reg .u64 t; cvta.to.shared.u64 t, %1; cvt.u32.u64 %0, t; }" : "=r"(a) : "l"(p));
    return a;
}
__device__ __forceinline__ void cp16(uint32_t dst, const void* src) {
    asm volatile("cp.async.cg.shared.global [%0], [%1], 16;" :: "r"(dst), "l"(src) : "memory");
}
__device__ __forceinline__ void cp_commit() { asm volatile("cp.async.commit_group;" ::: "memory"); }
template <int N> __device__ __forceinline__ void cp_wait() {
    asm volatile("cp.async.wait_group %0;" :: "n"(N) : "memory");
}
__device__ __forceinline__ void ldm_x4(uint32_t* r, uint32_t addr) {
    asm volatile("ldmatrix.sync.aligned.m8n8.x4.shared.b16 {%0,%1,%2,%3}, [%4];"
                 : "=r"(r[0]), "=r"(r[1]), "=r"(r[2]), "=r"(r[3]) : "r"(addr));
}
__device__ __forceinline__ void mma_f16(float* d, const uint32_t* a, uint32_t b0, uint32_t b1) {
    asm volatile(
        "mma.sync.aligned.m16n8k16.row.col.f32.f16.f16.f32 "
        "{%0,%1,%2,%3}, {%4,%5,%6,%7}, {%8,%9}, {%0,%1,%2,%3};"
        : "+f"(d[0]), "+f"(d[1]), "+f"(d[2]), "+f"(d[3])
        : "r"(a[0]), "r"(a[1]), "r"(a[2]), "r"(a[3]), "r"(b0), "r"(b1));
}

// ---- main hybrid kernel: 512 threads, 16 warps as 4(M) x 4(N), warp tile 32x32 ----

__global__ __launch_bounds__(512, 1)
void linbna_hybrid_kernel(const int* __restrict__ tvec,
                          const int* __restrict__ nvec,
                          const int* __restrict__ amin,
                          const int* __restrict__ amax,
                          float*     __restrict__ out)
{
    extern __shared__ char smem[];
    const uint32_t sb = smem_u32(smem);
    const int tid = threadIdx.x;
    const int wid = tid >> 5;
    const int lid = tid & 31;

    const int8_t* __restrict__ X = g_x;
    const int8_t* __restrict__ W = g_w;

    const int brow = blockIdx.y * BM;
    const int bcol = blockIdx.x * BN;

    if (tid < 128) {
        *(int*)(smem + OFF_PAR + 0    + tid * 4) = tvec[bcol + tid];
        *(int*)(smem + OFF_PAR + 512  + tid * 4) = nvec[bcol + tid];
        *(int*)(smem + OFF_PAR + 1024 + tid * 4) = amin[bcol + tid];
        *(int*)(smem + OFF_PAR + 1536 + tid * 4) = amax[bcol + tid];
    }

    // loader for pipeline group s3: H stage s3 (always, s3<86) + D chunk s3 (if s3<84)
    auto loader = [&](int s3) {
        const int rb = s3 & 3;
        const int kH = s3 * 32;
        {   // H: 512 cp16 ops, 1 per thread
            const int c   = tid & 255;
            const int row = c >> 1, ch = c & 1;
            if (tid < 256)
                cp16(sb + OFF_RAWH + rb * 8192 + row * 32 + ch * 16,
                     X + (size_t)(brow + row) * IN_DIM + kH + ch * 16);
            else
                cp16(sb + OFF_RAWH + rb * 8192 + 4096 + row * 32 + ch * 16,
                     W + (size_t)(bcol + row) * IN_DIM + kH + ch * 16);
        }
        if (s3 < D_CHUNKS) {   // D: 256 cp16 ops
            const int kD = KD_BASE + s3 * 16;
            if (tid < 128)
                cp16(sb + OFF_RAWD + rb * 4096 + tid * 16,
                     X + (size_t)(brow + tid) * IN_DIM + kD);
            else if (tid < 256) {
                const int r = tid - 128;
                cp16(sb + OFF_RAWD + rb * 4096 + 2048 + r * 16,
                     W + (size_t)(bcol + r) * IN_DIM + kD);
            }
        }
        cp_commit();
    };

    // int8 -> fp16 in-SMEM convert of raw H stage (rb) into f16 buffer fb
    auto convert = [&](int rb, int fb) {
        const int c   = tid & 255;
        const int row = c >> 1, hf = c & 1;
        const char* src = smem + OFF_RAWH + rb * 8192 + (tid < 256 ? 0 : 4096);
        char*       dst = smem + OFF_F16 + fb * 20480 + (tid < 256 ? 0 : 10240);
        const uint4 wv = *(const uint4*)(src + row * 32 + hf * 16);
        const uint32_t* pw = (const uint32_t*)&wv;
        uint32_t o[8];
        const __half2 bias = __half2half2(__ushort_as_half(0x6480));  // 1152.0
#pragma unroll
        for (int w = 0; w < 4; w++) {
            const uint32_t xv = pw[w] ^ 0x80808080u;
            uint32_t lo = __byte_perm(xv, 0x64646464u, 0x4140);
            uint32_t hi = __byte_perm(xv, 0x64646464u, 0x4342);
            __half2 hl = __hsub2(*(__half2*)&lo, bias);
            __half2 hh = __hsub2(*(__half2*)&hi, bias);
            o[2 * w]     = *(uint32_t*)&hl;
            o[2 * w + 1] = *(uint32_t*)&hh;
        }
        *(uint4*)(dst + row * RS + hf * 32)      = *(uint4*)&o[0];
        *(uint4*)(dst + row * RS + hf * 32 + 16) = *(uint4*)&o[4];
    };

    const int wm = wid & 3;       // M group (rows wm*32..+31)
    const int wn = wid >> 2;      // N group (cols wn*32..+31)
    const int sub = lid >> 3;
    const int srow = lid & 7;

    float accF[2][4][4];
    int   accI[2][4][4];
#pragma unroll
    for (int mt = 0; mt < 2; mt++)
#pragma unroll
        for (int nt = 0; nt < 4; nt++)
#pragma unroll
            for (int k = 0; k < 4; k++) { accF[mt][nt][k] = 0.0f; accI[mt][nt][k] = 0; }

    // prologue: 3 groups in flight, convert stage 0
    loader(0); loader(1); loader(2);
    cp_wait<2>();
    __syncthreads();
    convert(0, 0);

    for (int i = 0; i < ITERS; i++) {
        const int bb = i & 1;
        if (i >= ITERS - 2) cp_wait<0>(); else cp_wait<1>();
        __syncthreads();

        // --- HMMA on f16[bb] (issues first; tensor pipe grinds while ALU work follows)
        {
            const uint32_t fA = sb + OFF_F16 + bb * 20480;
            const uint32_t fB = fA + 10240;
#pragma unroll
            for (int s = 0; s < 2; s++) {
                uint32_t afr[2][4];
#pragma unroll
                for (int mt = 0; mt < 2; mt++) {
                    const int row = wm * 32 + mt * 16 + (sub & 1) * 8 + srow;
                    const int ch  = 2 * s + (sub >> 1);
                    ldm_x4(afr[mt], fA + row * RS + ch * 16);
                }
                uint32_t bfr[2][4];
#pragma unroll
                for (int bq = 0; bq < 2; bq++) {
                    const int nrow = wn * 32 + bq * 16 + (sub >> 1) * 8 + srow;
                    const int ch   = 2 * s + (sub & 1);
                    ldm_x4(bfr[bq], fB + nrow * RS + ch * 16);
                }
#pragma unroll
                for (int mt = 0; mt < 2; mt++)
#pragma unroll
                    for (int nt = 0; nt < 4; nt++)
                        mma_f16(accF[mt][nt], afr[mt],
                                bfr[nt >> 1][(nt & 1) * 2], bfr[nt >> 1][(nt & 1) * 2 + 1]);
            }
        }

        // --- prefetch group i+3
        if (i < ITERS - 3) loader(i + 3);

        // --- convert H stage i+1 into the other f16 buffer
        if (i + 1 < H_STAGES) convert((i + 1) & 3, bb ^ 1);

        // --- dp4a co-compute on raw D chunk i (4 k-words) in the HMMA shadow
        if (i < D_CHUNKS) {
            const char* dA = smem + OFF_RAWD + (i & 3) * 4096;
            const char* dB = dA + 2048;
            const int ra  = wm * 32 + (lid >> 2);
            const int cb0 = wn * 32 + 2 * (lid & 3);
#pragma unroll
            for (int kw = 0; kw < 4; kw++) {
                int av[2][2], bv[4][2];
#pragma unroll
                for (int mt = 0; mt < 2; mt++)
#pragma unroll
                    for (int u = 0; u < 2; u++)
                        av[mt][u] = *(const int*)(dA + (ra + mt * 16 + u * 8) * 16 + kw * 4);
#pragma unroll
                for (int nt = 0; nt < 4; nt++)
#pragma unroll
                    for (int v = 0; v < 2; v++)
                        bv[nt][v] = *(const int*)(dB + (cb0 + nt * 8 + v) * 16 + kw * 4);
#pragma unroll
                for (int mt = 0; mt < 2; mt++)
#pragma unroll
                    for (int nt = 0; nt < 4; nt++)
#pragma unroll
                        for (int u = 0; u < 2; u++)
#pragma unroll
                            for (int v = 0; v < 2; v++)
                                accI[mt][nt][u * 2 + v] =
                                    __dp4a(av[mt][u], bv[nt][v], accI[mt][nt][u * 2 + v]);
            }
        }
    }

    // ---- epilogue: merge float + int partial sums, requantize, store f32
    const int* sT  = (const int*)(smem + OFF_PAR);
    const int* sN  = (const int*)(smem + OFF_PAR + 512);
    const int* sLo = (const int*)(smem + OFF_PAR + 1024);
    const int* sHi = (const int*)(smem + OFF_PAR + 1536);

    const int r0 = brow + wm * 32 + (lid >> 2);
    const int cb = wn * 32 + 2 * (lid & 3);

#pragma unroll
    for (int mt = 0; mt < 2; mt++) {
#pragma unroll
        for (int nt = 0; nt < 4; nt++) {
            const int c  = cb + nt * 8;
            const int gc = bcol + c;
            const int t0 = sT[c],  t1 = sT[c + 1];
            const int s0 = -sN[c], s1 = -sN[c + 1];
            const int l0 = sLo[c], l1 = sLo[c + 1];
            const int h0 = sHi[c], h1 = sHi[c + 1];

            int v00 = (__float2int_rn(accF[mt][nt][0]) + accI[mt][nt][0] + t0) >> s0;
            int v01 = (__float2int_rn(accF[mt][nt][1]) + accI[mt][nt][1] + t1) >> s1;
            int v10 = (__float2int_rn(accF[mt][nt][2]) + accI[mt][nt][2] + t0) >> s0;
            int v11 = (__float2int_rn(accF[mt][nt][3]) + accI[mt][nt][3] + t1) >> s1;
            v00 = min(max(v00, l0), h0);  v01 = min(max(v01, l1), h1);
            v10 = min(max(v10, l0), h0);  v11 = min(max(v11, l1), h1);

            const int ra = r0 + mt * 16;
            float2 qa = { (float)v00, (float)v01 };
            float2 qb = { (float)v10, (float)v11 };
            *(float2*)(out + (size_t)ra * OUT_DIM + gc)       = qa;
            *(float2*)(out + (size_t)(ra + 8) * OUT_DIM + gc) = qb;
        }
    }
}

extern "C" void kernel_launch(void* const* d_in, const int* in_sizes, int n_in,
                              void* d_out, int out_size)
{
    const void* x   = d_in[0];
    const void* w   = d_in[1];
    const int* t    = (const int*)d_in[2];
    const int* n    = (const int*)d_in[3];
    const int* lo   = (const int*)d_in[4];
    const int* hi   = (const int*)d_in[5];

    static bool attr_set = false;
    if (!attr_set) {
        cudaFuncSetAttribute(linbna_hybrid_kernel,
                             cudaFuncAttributeMaxDynamicSharedMemorySize, SMEM_TOTAL);
        attr_set = true;
    }

    probe_kernel<<<1, 32>>>(x);
    repack_kernel<<<1184, 256>>>(x, w);
    dim3 grid(OUT_DIM / BN, B_DIM / BM);   // (32, 64)
    linbna_hybrid_kernel<<<grid, 512, SMEM_TOTAL>>>(t, n, lo, hi, (float*)d_out);
}

// round 10
// speedup vs baseline: 1.1593x; 1.1593x over previous
#include <cuda_runtime.h>
#include <cuda_bf16.h>
#include <cuda_fp16.h>
#include <stdint.h>

// LinBnA_int on GB300 via compute_103 (no tcgen05; legacy HMMA is the only real tensor path).
// Hybrid v2: K [0,3648) -> HMMA m16n8k16 (fp16, f32 accum, exact); K [3648,4096) -> dp4a
// dosed at 1 k-word per HMMA window so it hides in idle issue slots. Output f32.

static constexpr int B_DIM   = 8192;
static constexpr int IN_DIM  = 4096;
static constexpr int OUT_DIM = 4096;

static constexpr int BM = 128;
static constexpr int BN = 128;
static constexpr int RS = 80;                 // fp16 smem row stride (64B data + 16 pad)

static constexpr int H_STAGES = 114;          // 114 * 32 = 3648 K via HMMA
static constexpr int KD_BASE  = H_STAGES * 32;
static constexpr int KD_LEN   = IN_DIM - KD_BASE;   // 448
static constexpr int D_KWORDS = KD_LEN / 4;         // 112 (1 per window, windows 0..111)
static constexpr int D_CHUNKS = KD_LEN / 16;        // 28 chunks of 4 kwords

// dynamic SMEM layout
static constexpr int OFF_H   = 0;                   // 2 bufs x (A 10240 + B 10240) = 40960
static constexpr int OFF_D   = 40960;               // 2 bufs x (A 2048 + B 2048) = 8192
static constexpr int OFF_PAR = 49152;               // 4 x 128 x 4 = 2048
static constexpr int SMEM_TOTAL = 51200;

// mode: 0 = raw int8, 1 = int32, 2 = float32, 3 = bfloat16
__device__ int g_mode;
__device__ __align__(128) __half  g_xh[(size_t)B_DIM * IN_DIM];        // 64 MB
__device__ __align__(128) __half  g_wh[(size_t)OUT_DIM * IN_DIM];      // 32 MB
__device__ __align__(128) int8_t  g_xi[(size_t)B_DIM * KD_LEN];        // 3.5 MB
__device__ __align__(128) int8_t  g_wi[(size_t)OUT_DIM * KD_LEN];      // 1.75 MB

__global__ void probe_kernel(const void* x)
{
    if (threadIdx.x != 0) return;
    const uint32_t* w32 = (const uint32_t*)x;
    bool is_i32 = true, is_f32 = true;
    for (int i = 0; i < 32; i++) {
        uint32_t u = w32[i];
        int32_t v = (int32_t)u;
        if (!(v >= -128 && v < 128)) is_i32 = false;
        float f = __uint_as_float(u);
        if (!(isfinite(f) && f == truncf(f) && fabsf(f) <= 128.0f)) is_f32 = false;
    }
    bool is_b16 = true;
    const __nv_bfloat16* h = (const __nv_bfloat16*)x;
    for (int i = 0; i < 64; i++) {
        float f = __bfloat162float(h[i]);
        if (!(isfinite(f) && f == truncf(f) && fabsf(f) <= 128.0f)) is_b16 = false;
    }
    int m = 0;
    if (is_f32)      m = 2;
    else if (is_i32) m = 1;
    else if (is_b16) m = 3;
    g_mode = m;
}

// x/W (any encoding) -> fp16 arrays; K-tail also -> int8 side arrays for dp4a.
__global__ void repack_kernel(const void* xsrc, const void* wsrc)
{
    const int m = g_mode;
    const size_t NX = (size_t)B_DIM * IN_DIM;
    const size_t NW = (size_t)OUT_DIM * IN_DIM;
    const size_t total = NX + NW;
    const size_t stride = (size_t)gridDim.x * blockDim.x;
    for (size_t i = (size_t)blockIdx.x * blockDim.x + threadIdx.x; i < total; i += stride) {
        size_t xi; const void* src; __half* dsth; int8_t* dsti;
        if (i < NX) { xi = i;      src = xsrc; dsth = g_xh; dsti = g_xi; }
        else        { xi = i - NX; src = wsrc; dsth = g_wh; dsti = g_wi; }
        int v;
        if (m == 0)      v = (int)((const int8_t*)src)[xi];
        else if (m == 1) v = ((const int*)src)[xi];
        else if (m == 2) v = (int)((const float*)src)[xi];
        else             v = (int)__bfloat162float(((const __nv_bfloat16*)src)[xi]);
        dsth[xi] = __int2half_rn(v);
        const int k = (int)(xi & (IN_DIM - 1));
        if (k >= KD_BASE)
            dsti[(xi >> 12) * KD_LEN + (k - KD_BASE)] = (int8_t)v;
    }
}

// ---- helpers --------------------------------------------------------------

__device__ __forceinline__ uint32_t smem_u32(const void* p) {
    uint32_t a;
    asm("{ .reg .u64 t; cvta.to.shared.u64 t, %1; cvt.u32.u64 %0, t; }" : "=r"(a) : "l"(p));
    return a;
}
__device__ __forceinline__ void cp16(uint32_t dst, const void* src) {
    asm volatile("cp.async.cg.shared.global [%0], [%1], 16;" :: "r"(dst), "l"(src) : "memory");
}
__device__ __forceinline__ void cp_commit() { asm volatile("cp.async.commit_group;" ::: "memory"); }
template <int N> __device__ __forceinline__ void cp_wait() {
    asm volatile("cp.async.wait_group %0;" :: "n"(N) : "memory");
}
__device__ __forceinline__ void ldm_x4(uint32_t* r, uint32_t addr) {
    asm volatile("ldmatrix.sync.aligned.m8n8.x4.shared.b16 {%0,%1,%2,%3}, [%4];"
                 : "=r"(r[0]), "=r"(r[1]), "=r"(r[2]), "=r"(r[3]) : "r"(addr));
}
__device__ __forceinline__ void mma_f16(float* d, const uint32_t* a, uint32_t b0, uint32_t b1) {
    asm volatile(
        "mma.sync.aligned.m16n8k16.row.col.f32.f16.f16.f32 "
        "{%0,%1,%2,%3}, {%4,%5,%6,%7}, {%8,%9}, {%0,%1,%2,%3};"
        : "+f"(d[0]), "+f"(d[1]), "+f"(d[2]), "+f"(d[3])
        : "r"(a[0]), "r"(a[1]), "r"(a[2]), "r"(a[3]), "r"(b0), "r"(b1));
}

// ---- main kernel: 512 threads, 16 warps as 4(M) x 4(N), warp tile 32x32 ----

__global__ __launch_bounds__(512, 1)
void linbna_hybrid2_kernel(const int* __restrict__ tvec,
                           const int* __restrict__ nvec,
                           const int* __restrict__ amin,
                           const int* __restrict__ amax,
                           float*     __restrict__ out)
{
    extern __shared__ char smem[];
    const uint32_t sb = smem_u32(smem);
    const int tid = threadIdx.x;
    const int wid = tid >> 5;
    const int lid = tid & 31;

    const int brow = blockIdx.y * BM;
    const int bcol = blockIdx.x * BN;

    if (tid < 128) {
        *(int*)(smem + OFF_PAR + 0    + tid * 4) = tvec[bcol + tid];
        *(int*)(smem + OFF_PAR + 512  + tid * 4) = nvec[bcol + tid];
        *(int*)(smem + OFF_PAR + 1024 + tid * 4) = amin[bcol + tid];
        *(int*)(smem + OFF_PAR + 1536 + tid * 4) = amax[bcol + tid];
    }

    // loader(s): fp16 H-stage s (A and B, 1 cp16 each per thread) + every 4th stage one
    // int8 D-chunk (16B per row, threads 0..255).
    auto loader = [&](int s) {
        const int hb = s & 1;
        const int row = tid >> 2, ch = tid & 3;
        cp16(sb + OFF_H + hb * 20480 + row * RS + ch * 16,
             g_xh + (size_t)(brow + row) * IN_DIM + s * 32 + ch * 8);
        cp16(sb + OFF_H + hb * 20480 + 10240 + row * RS + ch * 16,
             g_wh + (size_t)(bcol + row) * IN_DIM + s * 32 + ch * 8);
        if ((s & 3) == 0 && (s >> 2) < D_CHUNKS) {
            const int c = s >> 2, db = c & 1;
            if (tid < 128)
                cp16(sb + OFF_D + db * 4096 + tid * 16,
                     g_xi + (size_t)(brow + tid) * KD_LEN + c * 16);
            else if (tid < 256) {
                const int r = tid - 128;
                cp16(sb + OFF_D + db * 4096 + 2048 + r * 16,
                     g_wi + (size_t)(bcol + r) * KD_LEN + c * 16);
            }
        }
        cp_commit();
    };

    const int wm = wid & 3;       // M group (rows wm*32..+31)
    const int wn = wid >> 2;      // N group (cols wn*32..+31)
    const int sub = lid >> 3;
    const int srow = lid & 7;

    float accF[2][4][4];
    int   accI[2][4][4];
#pragma unroll
    for (int mt = 0; mt < 2; mt++)
#pragma unroll
        for (int nt = 0; nt < 4; nt++)
#pragma unroll
            for (int k = 0; k < 4; k++) { accF[mt][nt][k] = 0.0f; accI[mt][nt][k] = 0; }

    loader(0);

    for (int i = 0; i < H_STAGES; i++) {
        const int bb = i & 1;
        if (i + 1 < H_STAGES) { loader(i + 1); cp_wait<1>(); }
        else                  { cp_wait<0>(); }
        __syncthreads();

        // --- HMMA on fp16 buffer bb
        {
            const uint32_t fA = sb + OFF_H + bb * 20480;
            const uint32_t fB = fA + 10240;
#pragma unroll
            for (int s = 0; s < 2; s++) {
                uint32_t afr[2][4];
#pragma unroll
                for (int mt = 0; mt < 2; mt++) {
                    const int row = wm * 32 + mt * 16 + (sub & 1) * 8 + srow;
                    const int ch  = 2 * s + (sub >> 1);
                    ldm_x4(afr[mt], fA + row * RS + ch * 16);
                }
                uint32_t bfr[2][4];
#pragma unroll
                for (int bq = 0; bq < 2; bq++) {
                    const int nrow = wn * 32 + bq * 16 + (sub >> 1) * 8 + srow;
                    const int ch   = 2 * s + (sub & 1);
                    ldm_x4(bfr[bq], fB + nrow * RS + ch * 16);
                }
#pragma unroll
                for (int mt = 0; mt < 2; mt++)
#pragma unroll
                    for (int nt = 0; nt < 4; nt++)
                        mma_f16(accF[mt][nt], afr[mt],
                                bfr[nt >> 1][(nt & 1) * 2], bfr[nt >> 1][(nt & 1) * 2 + 1]);
            }
        }

        // --- dp4a co-compute: exactly 1 k-word (4 K) in the HMMA shadow
        if (i < D_KWORDS) {
            const int chunk = i >> 2, q = i & 3;
            const char* dA = smem + OFF_D + (chunk & 1) * 4096;
            const char* dB = dA + 2048;
            const int ra  = wm * 32 + (lid >> 2);
            const int cb0 = wn * 32 + 2 * (lid & 3);
            int av[2][2], bv[4][2];
#pragma unroll
            for (int mt = 0; mt < 2; mt++)
#pragma unroll
                for (int u = 0; u < 2; u++)
                    av[mt][u] = *(const int*)(dA + (ra + mt * 16 + u * 8) * 16 + q * 4);
#pragma unroll
            for (int nt = 0; nt < 4; nt++)
#pragma unroll
                for (int v = 0; v < 2; v++)
                    bv[nt][v] = *(const int*)(dB + (cb0 + nt * 8 + v) * 16 + q * 4);
#pragma unroll
            for (int mt = 0; mt < 2; mt++)
#pragma unroll
                for (int nt = 0; nt < 4; nt++)
#pragma unroll
                    for (int u = 0; u < 2; u++)
#pragma unroll
                        for (int v = 0; v < 2; v++)
                            accI[mt][nt][u * 2 + v] =
                                __dp4a(av[mt][u], bv[nt][v], accI[mt][nt][u * 2 + v]);
        }

        __syncthreads();
    }

    // ---- epilogue: merge float + int partials, requantize, store f32
    const int* sT  = (const int*)(smem + OFF_PAR);
    const int* sN  = (const int*)(smem + OFF_PAR + 512);
    const int* sLo = (const int*)(smem + OFF_PAR + 1024);
    const int* sHi = (const int*)(smem + OFF_PAR + 1536);

    const int r0 = brow + wm * 32 + (lid >> 2);
    const int cb = wn * 32 + 2 * (lid & 3);

#pragma unroll
    for (int mt = 0; mt < 2; mt++) {
#pragma unroll
        for (int nt = 0; nt < 4; nt++) {
            const int c  = cb + nt * 8;
            const int gc = bcol + c;
            const int t0 = sT[c],  t1 = sT[c + 1];
            const int s0 = -sN[c], s1 = -sN[c + 1];
            const int l0 = sLo[c], l1 = sLo[c + 1];
            const int h0 = sHi[c], h1 = sHi[c + 1];

            int v00 = (__float2int_rn(accF[mt][nt][0]) + accI[mt][nt][0] + t0) >> s0;
            int v01 = (__float2int_rn(accF[mt][nt][1]) + accI[mt][nt][1] + t1) >> s1;
            int v10 = (__float2int_rn(accF[mt][nt][2]) + accI[mt][nt][2] + t0) >> s0;
            int v11 = (__float2int_rn(accF[mt][nt][3]) + accI[mt][nt][3] + t1) >> s1;
            v00 = min(max(v00, l0), h0);  v01 = min(max(v01, l1), h1);
            v10 = min(max(v10, l0), h0);  v11 = min(max(v11, l1), h1);

            const int ra = r0 + mt * 16;
            float2 qa = { (float)v00, (float)v01 };
            float2 qb = { (float)v10, (float)v11 };
            *(float2*)(out + (size_t)ra * OUT_DIM + gc)       = qa;
            *(float2*)(out + (size_t)(ra + 8) * OUT_DIM + gc) = qb;
        }
    }
}

extern "C" void kernel_launch(void* const* d_in, const int* in_sizes, int n_in,
                              void* d_out, int out_size)
{
    const void* x   = d_in[0];
    const void* w   = d_in[1];
    const int* t    = (const int*)d_in[2];
    const int* n    = (const int*)d_in[3];
    const int* lo   = (const int*)d_in[4];
    const int* hi   = (const int*)d_in[5];

    static bool attr_set = false;
    if (!attr_set) {
        cudaFuncSetAttribute(linbna_hybrid2_kernel,
                             cudaFuncAttributeMaxDynamicSharedMemorySize, SMEM_TOTAL);
        attr_set = true;
    }

    probe_kernel<<<1, 32>>>(x);
    repack_kernel<<<1184, 256>>>(x, w);
    dim3 grid(OUT_DIM / BN, B_DIM / BM);   // (32, 64)
    linbna_hybrid2_kernel<<<grid, 512, SMEM_TOTAL>>>(t, n, lo, hi, (float*)d_out);
}